// round 11
// baseline (speedup 1.0000x reference)
#include <cuda_runtime.h>
#include <cuda_bf16.h>
#include <cstdint>

#define NN  50000
#define EMBD 128
#define NE  500000
#define K2_TILES ((NE + 63) / 64)      // 7813
#define K2_GRID  444                   // 148 SMs * 3 CTAs

// scratch (allocation-free rule: __device__ globals)
__device__ __align__(16) float g_H1[NN * EMBD];
__device__ __align__(16) float g_acc[NN * EMBD];
__device__ unsigned g_mask[NN * 4];   // dropout keep-bits, 4 words/row
// pre-split bf16 images (row-major [k][n])
__device__ __align__(16) uint4 g_W1img_hi[2048];  // 32KB, W_msg[0:128,:]
__device__ __align__(16) uint4 g_W1img_lo[2048];
__device__ __align__(16) uint4 g_Bimg_hi[1024];   // 16KB, W_msg[128:192,:]
__device__ __align__(16) uint4 g_Bimg_lo[1024];
__device__ __align__(16) uint4 g_WLimg_hi[2048];  // 32KB, W_lin
__device__ __align__(16) uint4 g_WLimg_lo[2048];

// ---------------------------------------------------------------------------
// threefry2x32, JAX partitionable mode. key=(0,42), counter=(0, flat),
// output = out0 ^ out1.
// ---------------------------------------------------------------------------
__device__ __forceinline__ unsigned tf_rotl(unsigned x, int r) {
    return __funnelshift_l(x, x, r);
}
__device__ __forceinline__ unsigned threefry_bits(unsigned flat) {
    unsigned x0 = 0u, x1 = flat;
    const unsigned ks0 = 0u, ks1 = 42u, ks2 = 0x1BD11BDAu ^ 0u ^ 42u;
    x0 += ks0; x1 += ks1;
#define TF_R(r) { x0 += x1; x1 = tf_rotl(x1, r); x1 ^= x0; }
    TF_R(13) TF_R(15) TF_R(26) TF_R(6)
    x0 += ks1; x1 += ks2 + 1u;
    TF_R(17) TF_R(29) TF_R(16) TF_R(24)
    x0 += ks2; x1 += ks0 + 2u;
    TF_R(13) TF_R(15) TF_R(26) TF_R(6)
    x0 += ks0; x1 += ks1 + 3u;
    TF_R(17) TF_R(29) TF_R(16) TF_R(24)
    x0 += ks1; x1 += ks2 + 4u;
    TF_R(13) TF_R(15) TF_R(26) TF_R(6)
    x0 += ks2; x1 += ks0 + 5u;
#undef TF_R
    return x0 ^ x1;
}

// ---------------------------------------------------------------------------
// baseline-PTX helpers
// ---------------------------------------------------------------------------
__device__ __forceinline__ uint32_t smem_u32(const void* p) {
    uint32_t a;
    asm("{ .reg .u64 t; cvta.to.shared.u64 t, %1; cvt.u32.u64 %0, t; }"
        : "=r"(a) : "l"(p));
    return a;
}
__device__ __forceinline__ void ldsm_x4(uint32_t addr, uint32_t* r) {
    asm volatile("ldmatrix.sync.aligned.m8n8.x4.shared.b16 {%0,%1,%2,%3}, [%4];"
                 : "=r"(r[0]), "=r"(r[1]), "=r"(r[2]), "=r"(r[3]) : "r"(addr));
}
__device__ __forceinline__ void ldsm_x4_t(uint32_t addr, uint32_t& r0, uint32_t& r1,
                                          uint32_t& r2, uint32_t& r3) {
    asm volatile("ldmatrix.sync.aligned.m8n8.x4.trans.shared.b16 {%0,%1,%2,%3}, [%4];"
                 : "=r"(r0), "=r"(r1), "=r"(r2), "=r"(r3) : "r"(addr));
}
__device__ __forceinline__ void mma16816(float* c, const uint32_t* a,
                                         uint32_t b0, uint32_t b1) {
    asm volatile(
        "mma.sync.aligned.m16n8k16.row.col.f32.bf16.bf16.f32 "
        "{%0,%1,%2,%3}, {%4,%5,%6,%7}, {%8,%9}, {%0,%1,%2,%3};"
        : "+f"(c[0]), "+f"(c[1]), "+f"(c[2]), "+f"(c[3])
        : "r"(a[0]), "r"(a[1]), "r"(a[2]), "r"(a[3]), "r"(b0), "r"(b1));
}
__device__ __forceinline__ void red_add_v2(float* p, float a, float b) {
    asm volatile("red.global.add.v2.f32 [%0], {%1, %2};"
                 :: "l"(p), "f"(a), "f"(b) : "memory");
}
__device__ __forceinline__ unsigned pack_bf2(__nv_bfloat16 a, __nv_bfloat16 b) {
    unsigned ua = (unsigned)__bfloat16_as_ushort(a);
    unsigned ub = (unsigned)__bfloat16_as_ushort(b);
    return ua | (ub << 16);
}
__device__ __forceinline__ void split_store(char* dh, char* dl, const float* xs) {
    unsigned hw[8], lw[8];
#pragma unroll
    for (int j = 0; j < 8; ++j) {
        __nv_bfloat16 h0 = __float2bfloat16(xs[j * 2 + 0]);
        __nv_bfloat16 h1 = __float2bfloat16(xs[j * 2 + 1]);
        __nv_bfloat16 l0 = __float2bfloat16(xs[j * 2 + 0] - __bfloat162float(h0));
        __nv_bfloat16 l1 = __float2bfloat16(xs[j * 2 + 1] - __bfloat162float(h1));
        hw[j] = pack_bf2(h0, h1);
        lw[j] = pack_bf2(l0, l1);
    }
    *(uint4*)dh        = make_uint4(hw[0], hw[1], hw[2], hw[3]);
    *(uint4*)(dh + 16) = make_uint4(hw[4], hw[5], hw[6], hw[7]);
    *(uint4*)dl        = make_uint4(lw[0], lw[1], lw[2], lw[3]);
    *(uint4*)(dl + 16) = make_uint4(lw[4], lw[5], lw[6], lw[7]);
}

// ---------------------------------------------------------------------------
// k0: split W_msg (24576) and W_lin (16384) into hi/lo bf16 images
// ---------------------------------------------------------------------------
__global__ __launch_bounds__(256) void k0_prep_w(const float* __restrict__ W_msg,
                                                 const float* __restrict__ W_lin) {
    int idx = blockIdx.x * 256 + threadIdx.x;      // 0..40959
    float x;
    if (idx < 24576) x = W_msg[idx];
    else             x = W_lin[idx - 24576];
    __nv_bfloat16 h = __float2bfloat16(x);
    __nv_bfloat16 l = __float2bfloat16(x - __bfloat162float(h));
    if (idx < 16384) {
        ((__nv_bfloat16*)g_W1img_hi)[idx] = h;
        ((__nv_bfloat16*)g_W1img_lo)[idx] = l;
    } else if (idx < 24576) {
        ((__nv_bfloat16*)g_Bimg_hi)[idx - 16384] = h;
        ((__nv_bfloat16*)g_Bimg_lo)[idx - 16384] = l;
    } else {
        ((__nv_bfloat16*)g_WLimg_hi)[idx - 24576] = h;
        ((__nv_bfloat16*)g_WLimg_lo)[idx - 24576] = l;
    }
}

// ---------------------------------------------------------------------------
// shared 128x128 HMMA GEMM body (K=128), 512 threads.
// CTA = 128 rows x 128 cols, 16 warps (4m x 4n), warp = 32r x 32c.
// ---------------------------------------------------------------------------
#define KQ_APITCH 272
#define KQ_BPITCH 272
#define KQ_AHI 0
#define KQ_ALO 34816
#define KQ_BHI 69632
#define KQ_BLO 104448
#define KQ_SMEM 139264

#define HMMA_128x128_BODY(SRC, BIMG_HI, BIMG_LO)                                   \
    const int tid = threadIdx.x;                                                   \
    const int lane = tid & 31, w = tid >> 5;                                       \
    {                                                                              \
        const uint4* bh = BIMG_HI;                                                 \
        const uint4* bl = BIMG_LO;                                                 \
        _Pragma("unroll")                                                          \
        for (int t = 0; t < 4; ++t) {                                              \
            int idx = tid + t * 512;                                               \
            int row = idx >> 4, seg = idx & 15;                                    \
            *(uint4*)(smc + KQ_BHI + row * KQ_BPITCH + seg * 16) = bh[idx];        \
            *(uint4*)(smc + KQ_BLO + row * KQ_BPITCH + seg * 16) = bl[idx];        \
        }                                                                          \
    }                                                                              \
    {                                                                              \
        int r = tid >> 2, q = tid & 3;                                             \
        int gr = row0 + r;                                                         \
        float xs[32];                                                              \
        if (gr < NN) {                                                             \
            const float4* p = (const float4*)(SRC + (size_t)gr * 128 + q * 32);    \
            _Pragma("unroll")                                                      \
            for (int i = 0; i < 8; ++i) {                                          \
                float4 f = p[i];                                                   \
                xs[i*4+0]=f.x; xs[i*4+1]=f.y; xs[i*4+2]=f.z; xs[i*4+3]=f.w;        \
            }                                                                      \
        } else {                                                                   \
            _Pragma("unroll")                                                      \
            for (int i = 0; i < 32; ++i) xs[i] = 0.f;                              \
        }                                                                          \
        split_store(smc + KQ_AHI + r * KQ_APITCH + q * 64,                         \
                    smc + KQ_ALO + r * KQ_APITCH + q * 64, xs);                    \
        split_store(smc + KQ_AHI + r * KQ_APITCH + q * 64 + 32,                    \
                    smc + KQ_ALO + r * KQ_APITCH + q * 64 + 32, xs + 16);          \
    }                                                                              \
    __syncthreads();                                                               \
    const int m0 = (w >> 2) * 32;                                                  \
    const int n0 = (w & 3) * 32;                                                   \
    float acc[2][4][4];                                                            \
    _Pragma("unroll")                                                              \
    for (int a = 0; a < 2; ++a)                                                    \
        _Pragma("unroll")                                                          \
        for (int b = 0; b < 4; ++b)                                                \
            _Pragma("unroll")                                                      \
            for (int c = 0; c < 4; ++c) acc[a][b][c] = 0.f;                        \
    const uint32_t arow = (uint32_t)(lane & 15);                                   \
    const uint32_t acol = (uint32_t)((lane >> 4) * 16);                            \
    _Pragma("unroll")                                                              \
    for (int k = 0; k < 8; ++k) {                                                  \
        uint32_t a0[4], a1[4];                                                     \
        uint32_t ad = sb + KQ_AHI + (uint32_t)(m0 + arow) * KQ_APITCH + k * 32 + acol; \
        ldsm_x4(ad, a0);                                                           \
        ldsm_x4(ad + 16 * KQ_APITCH, a1);                                          \
        _Pragma("unroll")                                                          \
        for (int p = 0; p < 2; ++p) {                                              \
            uint32_t bd = sb + KQ_BHI + (uint32_t)(k * 16 + arow) * KQ_BPITCH      \
                        + (uint32_t)(n0 + p * 16) * 2 + acol;                      \
            uint32_t h0,h1,h2,h3, l0,l1,l2,l3;                                     \
            ldsm_x4_t(bd, h0, h1, h2, h3);                                         \
            ldsm_x4_t(bd + (KQ_BLO - KQ_BHI), l0, l1, l2, l3);                     \
            mma16816(acc[0][p*2],   a0, h0, h1);                                   \
            mma16816(acc[0][p*2+1], a0, h2, h3);                                   \
            mma16816(acc[1][p*2],   a1, h0, h1);                                   \
            mma16816(acc[1][p*2+1], a1, h2, h3);                                   \
            mma16816(acc[0][p*2],   a0, l0, l1);                                   \
            mma16816(acc[0][p*2+1], a0, l2, l3);                                   \
            mma16816(acc[1][p*2],   a1, l0, l1);                                   \
            mma16816(acc[1][p*2+1], a1, l2, l3);                                   \
        }                                                                          \
    }                                                                              \
    _Pragma("unroll")                                                              \
    for (int k = 0; k < 8; ++k) {                                                  \
        uint32_t a0[4], a1[4];                                                     \
        uint32_t ad = sb + KQ_ALO + (uint32_t)(m0 + arow) * KQ_APITCH + k * 32 + acol; \
        ldsm_x4(ad, a0);                                                           \
        ldsm_x4(ad + 16 * KQ_APITCH, a1);                                          \
        _Pragma("unroll")                                                          \
        for (int p = 0; p < 2; ++p) {                                              \
            uint32_t bd = sb + KQ_BHI + (uint32_t)(k * 16 + arow) * KQ_BPITCH      \
                        + (uint32_t)(n0 + p * 16) * 2 + acol;                      \
            uint32_t h0,h1,h2,h3;                                                  \
            ldsm_x4_t(bd, h0, h1, h2, h3);                                         \
            mma16816(acc[0][p*2],   a0, h0, h1);                                   \
            mma16816(acc[0][p*2+1], a0, h2, h3);                                   \
            mma16816(acc[1][p*2],   a1, h0, h1);                                   \
            mma16816(acc[1][p*2+1], a1, h2, h3);                                   \
        }                                                                          \
    }

// ---------------------------------------------------------------------------
// k1: H1 = hidden @ W1 + b_msg   (128-row CTA, 512 thr)
// ---------------------------------------------------------------------------
__global__ __launch_bounds__(512, 1) void k1_node_hmma(
    const float* __restrict__ A, const float* __restrict__ bias,
    float* __restrict__ out)
{
    extern __shared__ char smc[];
    const uint32_t sb = smem_u32(smc);
    const int row0 = blockIdx.x * 128;
    HMMA_128x128_BODY(A, g_W1img_hi, g_W1img_lo)

#pragma unroll
    for (int mt = 0; mt < 2; ++mt) {
#pragma unroll
        for (int half = 0; half < 2; ++half) {
            int r = row0 + m0 + mt * 16 + (lane >> 2) + half * 8;
            if (r < NN) {
                float* o = out + (size_t)r * 128;
#pragma unroll
                for (int nt = 0; nt < 4; ++nt) {
                    int j = n0 + nt * 8 + (lane & 3) * 2;
                    float2 b2 = *(const float2*)(bias + j);
                    float2 v;
                    v.x = acc[mt][nt][half * 2 + 0] + b2.x;
                    v.y = acc[mt][nt][half * 2 + 1] + b2.y;
                    *(float2*)(o + j) = v;
                }
            }
        }
    }
}

// ---------------------------------------------------------------------------
// k2: PERSISTENT split-bf16 edge GEMM (HMMA) + gather/relu + red.v2 scatter.
// 444 CTAs (3/SM), each loops over 64-edge tiles. B images loaded into smem
// ONCE per CTA. Dropout mask generated per tile (same mapping as before).
// ---------------------------------------------------------------------------
#define K2_APITCH 144
#define K2_BPITCH 272
#define K2_AHI 0
#define K2_ALO 9216
#define K2_BHI 18432
#define K2_BLO 35840
#define K2_IDX 53248
#define K2_SMEM 53760

__global__ __launch_bounds__(256, 3) void k2_edge_mma(
    const float* __restrict__ eattr, const float* __restrict__ etime,
    const int* __restrict__ eidx, const float* __restrict__ H1,
    float* __restrict__ accum)
{
    extern __shared__ char smc[];
    const uint32_t sb = smem_u32(smc);
    const int tid = threadIdx.x;
    const int lane = tid & 31, w = tid >> 5;
    int* s_src = (int*)(smc + K2_IDX);
    int* s_dst = s_src + 64;

    // B images -> smem ONCE
    {
        const uint4* bh = g_Bimg_hi;
        const uint4* bl = g_Bimg_lo;
#pragma unroll
        for (int t = 0; t < 4; ++t) {
            int idx = tid + t * 256;            // row=idx>>4, seg=idx&15
            int row = idx >> 4, seg = idx & 15;
            *(uint4*)(smc + K2_BHI + row * K2_BPITCH + seg * 16) = bh[idx];
            *(uint4*)(smc + K2_BLO + row * K2_BPITCH + seg * 16) = bl[idx];
        }
    }

    const int m0 = (w >> 2) * 32;
    const int n0 = (w & 3) * 32;
    const uint32_t arow = (uint32_t)(lane & 15);
    const uint32_t acol = (uint32_t)((lane >> 4) * 16);
    const int ed = tid >> 2, q = tid & 3;

    for (int t = blockIdx.x; t < K2_TILES; t += K2_GRID) {
        const int e0 = t * 64;

        // indices for this tile
        if (tid < 128) {
            int r = tid & 63;
            int e = e0 + r;
            int v = (e < NE) ? eidx[(tid < 64 ? 0 : NE) + e] : 0;
            if (tid < 64) s_src[r] = v; else s_dst[r] = v;
        }
        // A tile: 64 edges x 64 f32, split hi/lo
        {
            int e = e0 + ed;
            float xs[16];
            if (e < NE) {
                const float4* p = (q < 2) ? ((const float4*)(eattr + (size_t)e * 32) + q * 4)
                                          : ((const float4*)(etime + (size_t)e * 32) + (q - 2) * 4);
                float4 f0 = p[0], f1 = p[1], f2 = p[2], f3 = p[3];
                xs[0]=f0.x; xs[1]=f0.y; xs[2]=f0.z; xs[3]=f0.w;
                xs[4]=f1.x; xs[5]=f1.y; xs[6]=f1.z; xs[7]=f1.w;
                xs[8]=f2.x; xs[9]=f2.y; xs[10]=f2.z; xs[11]=f2.w;
                xs[12]=f3.x; xs[13]=f3.y; xs[14]=f3.z; xs[15]=f3.w;
            } else {
#pragma unroll
                for (int i = 0; i < 16; ++i) xs[i] = 0.f;
            }
            split_store(smc + K2_AHI + ed * K2_APITCH + q * 32,
                        smc + K2_ALO + ed * K2_APITCH + q * 32, xs);
        }
        // dropout keep-mask for node row W = t*8 + w (same mapping as R8-R10)
        {
            int W = t * 8 + w;
            if (W < NN) {
#pragma unroll
                for (int k = 0; k < 4; ++k) {
                    unsigned flat = (unsigned)(W * 128 + lane * 4 + k);
                    unsigned bits = threefry_bits(flat);
                    float u = __uint_as_float((bits >> 9) | 0x3F800000u) - 1.0f;
                    unsigned bal = __ballot_sync(0xffffffffu, u < 0.9f);
                    if (lane == k) g_mask[W * 4 + k] = bal;
                }
            }
        }
        __syncthreads();

        float acc[2][4][4];
#pragma unroll
        for (int a = 0; a < 2; ++a)
#pragma unroll
            for (int b = 0; b < 4; ++b)
#pragma unroll
                for (int c = 0; c < 4; ++c) acc[a][b][c] = 0.f;

#pragma unroll
        for (int k = 0; k < 4; ++k) {
            uint32_t a0[4], a1[4];
            uint32_t ad = sb + K2_AHI + (uint32_t)(m0 + arow) * K2_APITCH + k * 32 + acol;
            ldsm_x4(ad, a0);
            ldsm_x4(ad + 16 * K2_APITCH, a1);
#pragma unroll
            for (int p = 0; p < 2; ++p) {
                uint32_t bd = sb + K2_BHI + (uint32_t)(k * 16 + arow) * K2_BPITCH
                            + (uint32_t)(n0 + p * 16) * 2 + acol;
                uint32_t h0,h1,h2,h3, l0,l1,l2,l3;
                ldsm_x4_t(bd, h0, h1, h2, h3);
                ldsm_x4_t(bd + (K2_BLO - K2_BHI), l0, l1, l2, l3);
                mma16816(acc[0][p*2],   a0, h0, h1);
                mma16816(acc[0][p*2+1], a0, h2, h3);
                mma16816(acc[1][p*2],   a1, h0, h1);
                mma16816(acc[1][p*2+1], a1, h2, h3);
                mma16816(acc[0][p*2],   a0, l0, l1);
                mma16816(acc[0][p*2+1], a0, l2, l3);
                mma16816(acc[1][p*2],   a1, l0, l1);
                mma16816(acc[1][p*2+1], a1, l2, l3);
            }
        }
#pragma unroll
        for (int k = 0; k < 4; ++k) {
            uint32_t a0[4], a1[4];
            uint32_t ad = sb + K2_ALO + (uint32_t)(m0 + arow) * K2_APITCH + k * 32 + acol;
            ldsm_x4(ad, a0);
            ldsm_x4(ad + 16 * K2_APITCH, a1);
#pragma unroll
            for (int p = 0; p < 2; ++p) {
                uint32_t bd = sb + K2_BHI + (uint32_t)(k * 16 + arow) * K2_BPITCH
                            + (uint32_t)(n0 + p * 16) * 2 + acol;
                uint32_t h0,h1,h2,h3;
                ldsm_x4_t(bd, h0, h1, h2, h3);
                mma16816(acc[0][p*2],   a0, h0, h1);
                mma16816(acc[0][p*2+1], a0, h2, h3);
                mma16816(acc[1][p*2],   a1, h0, h1);
                mma16816(acc[1][p*2+1], a1, h2, h3);
            }
        }

        // epilogue: gather H1[src], relu, red.v2 into acc[dst]
#pragma unroll
        for (int mt = 0; mt < 2; ++mt) {
#pragma unroll
            for (int half = 0; half < 2; ++half) {
                int r = m0 + mt * 16 + (lane >> 2) + half * 8;
                if (e0 + r < NE) {
                    const float* hp = H1 + (size_t)s_src[r] * 128;
                    float* ap = accum + (size_t)s_dst[r] * 128;
#pragma unroll
                    for (int nt = 0; nt < 4; ++nt) {
                        int j = n0 + nt * 8 + (lane & 3) * 2;
                        float2 h = *(const float2*)(hp + j);
                        red_add_v2(ap + j,
                                   fmaxf(acc[mt][nt][half * 2 + 0] + h.x, 0.f),
                                   fmaxf(acc[mt][nt][half * 2 + 1] + h.y, 0.f));
                    }
                }
            }
        }
        __syncthreads();   // protect s_src/s_dst + A smem before next iteration
    }
}

// ---------------------------------------------------------------------------
// k3: out = dropout(relu(LN(acc @ W_lin + b_lin)))  — 128-row CTA, 512 thr,
// smem-staged LN epilogue (warp per row), mask read from g_mask.
// ---------------------------------------------------------------------------
#define K3_OPITCH 132

__global__ __launch_bounds__(512, 1) void k3_hmma(
    const float* __restrict__ A, const float* __restrict__ bias,
    const float* __restrict__ gamma, const float* __restrict__ beta,
    float* __restrict__ out)
{
    extern __shared__ char smc[];
    const uint32_t sb = smem_u32(smc);
    const int row0 = blockIdx.x * 128;
    HMMA_128x128_BODY(A, g_WLimg_hi, g_WLimg_lo)

    __syncthreads();
    float* so = (float*)smc;   // 128 rows x K3_OPITCH floats
#pragma unroll
    for (int mt = 0; mt < 2; ++mt) {
#pragma unroll
        for (int half = 0; half < 2; ++half) {
            int rl = m0 + mt * 16 + (lane >> 2) + half * 8;
#pragma unroll
            for (int nt = 0; nt < 4; ++nt) {
                int j = n0 + nt * 8 + (lane & 3) * 2;
                float2 v;
                v.x = acc[mt][nt][half * 2 + 0];
                v.y = acc[mt][nt][half * 2 + 1];
                *(float2*)(so + rl * K3_OPITCH + j) = v;
            }
        }
    }
    __syncthreads();

    const int tx = lane;
    float bb[4] = { bias[tx], bias[tx + 32], bias[tx + 64], bias[tx + 96] };
    float gm[4] = { gamma[tx], gamma[tx + 32], gamma[tx + 64], gamma[tx + 96] };
    float bt[4] = { beta[tx],  beta[tx + 32],  beta[tx + 64],  beta[tx + 96] };

#pragma unroll
    for (int i = 0; i < 8; ++i) {
        int rl = w * 8 + i;
        int r = row0 + rl;
        float v[4];
#pragma unroll
        for (int c = 0; c < 4; ++c) v[c] = so[rl * K3_OPITCH + tx + 32 * c] + bb[c];
        float s = v[0] + v[1] + v[2] + v[3];
#pragma unroll
        for (int off = 16; off; off >>= 1) s += __shfl_xor_sync(0xffffffffu, s, off);
        float mean = s * (1.0f / 128.0f);
        float d[4];
        float ss = 0.f;
#pragma unroll
        for (int c = 0; c < 4; ++c) { d[c] = v[c] - mean; ss += d[c] * d[c]; }
#pragma unroll
        for (int off = 16; off; off >>= 1) ss += __shfl_xor_sync(0xffffffffu, ss, off);
        float rstd = rsqrtf(ss * (1.0f / 128.0f) + 1e-5f);

        if (r < NN) {
            float* o = out + (size_t)r * 128;
            unsigned mw = g_mask[r * 4 + (tx & 3)];
#pragma unroll
            for (int c = 0; c < 4; ++c) {
                int j = tx + 32 * c;
                float y = d[c] * rstd * gm[c] + bt[c];
                y = fmaxf(y, 0.f);
                unsigned bit = (unsigned)(8 * c + (tx >> 2));
                o[j] = ((mw >> bit) & 1u) ? (y * (1.0f / 0.9f)) : 0.f;
            }
        }
    }
}

// ---------------------------------------------------------------------------
extern "C" void kernel_launch(void* const* d_in, const int* in_sizes, int n_in,
                              void* d_out, int out_size) {
    (void)in_sizes; (void)n_in; (void)out_size;
    const float* hidden   = (const float*)d_in[0];
    const int*   eidx     = (const int*)d_in[1];
    const float* eattr    = (const float*)d_in[2];
    const float* etime    = (const float*)d_in[3];
    const float* boundary = (const float*)d_in[4];
    const float* W_msg    = (const float*)d_in[5];
    const float* b_msg    = (const float*)d_in[6];
    const float* W_lin    = (const float*)d_in[7];
    const float* b_lin    = (const float*)d_in[8];
    const float* gamma    = (const float*)d_in[9];
    const float* beta     = (const float*)d_in[10];
    float* out = (float*)d_out;

    void* h1Ptr = nullptr;
    void* accPtr = nullptr;
    cudaGetSymbolAddress(&h1Ptr, g_H1);
    cudaGetSymbolAddress(&accPtr, g_acc);

    cudaFuncSetAttribute(k1_node_hmma, cudaFuncAttributeMaxDynamicSharedMemorySize, KQ_SMEM);
    cudaFuncSetAttribute(k2_edge_mma,  cudaFuncAttributeMaxDynamicSharedMemorySize, K2_SMEM);
    cudaFuncSetAttribute(k3_hmma,      cudaFuncAttributeMaxDynamicSharedMemorySize, KQ_SMEM);

    // acc = boundary_condition (self-loop messages)
    cudaMemcpyAsync(accPtr, boundary, (size_t)NN * EMBD * sizeof(float),
                    cudaMemcpyDeviceToDevice, 0);

    // prep: split W_msg + W_lin into bf16 hi/lo images
    k0_prep_w<<<160, 256>>>(W_msg, W_lin);

    // H1 = hidden @ W_msg[0:128] + b_msg   (HMMA, 128-row CTAs)
    k1_node_hmma<<<(NN + 127) / 128, 512, KQ_SMEM>>>(hidden, b_msg, (float*)h1Ptr);

    // edge messages: persistent CTAs, B loaded once, mask gen folded in
    k2_edge_mma<<<K2_GRID, 256, K2_SMEM>>>(eattr, etime, eidx,
                                           (const float*)h1Ptr, (float*)accPtr);

    // node update: HMMA GEMM + LN + relu + mask-dropout (128-row CTAs)
    k3_hmma<<<(NN + 127) / 128, 512, KQ_SMEM>>>((const float*)accPtr, b_lin,
                                                gamma, beta, out);
}

// round 12
// speedup vs baseline: 1.0265x; 1.0265x over previous
#include <cuda_runtime.h>
#include <cuda_bf16.h>
#include <cstdint>

#define NN  50000
#define EMBD 128
#define NE  500000

// scratch (allocation-free rule: __device__ globals)
__device__ __align__(16) float g_H1[NN * EMBD];
__device__ __align__(16) float g_acc[NN * EMBD];
__device__ unsigned g_mask[NN * 4];   // dropout keep-bits, 4 words/row
// pre-split bf16 images (row-major [k][n])
__device__ __align__(16) uint4 g_W1img_hi[2048];  // 32KB, W_msg[0:128,:]
__device__ __align__(16) uint4 g_W1img_lo[2048];
__device__ __align__(16) uint4 g_Bimg_hi[1024];   // 16KB, W_msg[128:192,:]
__device__ __align__(16) uint4 g_Bimg_lo[1024];
__device__ __align__(16) uint4 g_WLimg_hi[2048];  // 32KB, W_lin
__device__ __align__(16) uint4 g_WLimg_lo[2048];

// ---------------------------------------------------------------------------
// threefry2x32, JAX partitionable mode. key=(0,42), counter=(0, flat),
// output = out0 ^ out1.
// ---------------------------------------------------------------------------
__device__ __forceinline__ unsigned tf_rotl(unsigned x, int r) {
    return __funnelshift_l(x, x, r);
}
__device__ __forceinline__ unsigned threefry_bits(unsigned flat) {
    unsigned x0 = 0u, x1 = flat;
    const unsigned ks0 = 0u, ks1 = 42u, ks2 = 0x1BD11BDAu ^ 0u ^ 42u;
    x0 += ks0; x1 += ks1;
#define TF_R(r) { x0 += x1; x1 = tf_rotl(x1, r); x1 ^= x0; }
    TF_R(13) TF_R(15) TF_R(26) TF_R(6)
    x0 += ks1; x1 += ks2 + 1u;
    TF_R(17) TF_R(29) TF_R(16) TF_R(24)
    x0 += ks2; x1 += ks0 + 2u;
    TF_R(13) TF_R(15) TF_R(26) TF_R(6)
    x0 += ks0; x1 += ks1 + 3u;
    TF_R(17) TF_R(29) TF_R(16) TF_R(24)
    x0 += ks1; x1 += ks2 + 4u;
    TF_R(13) TF_R(15) TF_R(26) TF_R(6)
    x0 += ks2; x1 += ks0 + 5u;
#undef TF_R
    return x0 ^ x1;
}

// ---------------------------------------------------------------------------
// baseline-PTX helpers
// ---------------------------------------------------------------------------
__device__ __forceinline__ uint32_t smem_u32(const void* p) {
    uint32_t a;
    asm("{ .reg .u64 t; cvta.to.shared.u64 t, %1; cvt.u32.u64 %0, t; }"
        : "=r"(a) : "l"(p));
    return a;
}
__device__ __forceinline__ void ldsm_x4(uint32_t addr, uint32_t* r) {
    asm volatile("ldmatrix.sync.aligned.m8n8.x4.shared.b16 {%0,%1,%2,%3}, [%4];"
                 : "=r"(r[0]), "=r"(r[1]), "=r"(r[2]), "=r"(r[3]) : "r"(addr));
}
__device__ __forceinline__ void ldsm_x4_t(uint32_t addr, uint32_t& r0, uint32_t& r1,
                                          uint32_t& r2, uint32_t& r3) {
    asm volatile("ldmatrix.sync.aligned.m8n8.x4.trans.shared.b16 {%0,%1,%2,%3}, [%4];"
                 : "=r"(r0), "=r"(r1), "=r"(r2), "=r"(r3) : "r"(addr));
}
__device__ __forceinline__ void mma16816(float* c, const uint32_t* a,
                                         uint32_t b0, uint32_t b1) {
    asm volatile(
        "mma.sync.aligned.m16n8k16.row.col.f32.bf16.bf16.f32 "
        "{%0,%1,%2,%3}, {%4,%5,%6,%7}, {%8,%9}, {%0,%1,%2,%3};"
        : "+f"(c[0]), "+f"(c[1]), "+f"(c[2]), "+f"(c[3])
        : "r"(a[0]), "r"(a[1]), "r"(a[2]), "r"(a[3]), "r"(b0), "r"(b1));
}
__device__ __forceinline__ void red_add_v2(float* p, float a, float b) {
    asm volatile("red.global.add.v2.f32 [%0], {%1, %2};"
                 :: "l"(p), "f"(a), "f"(b) : "memory");
}
__device__ __forceinline__ unsigned pack_bf2(__nv_bfloat16 a, __nv_bfloat16 b) {
    unsigned ua = (unsigned)__bfloat16_as_ushort(a);
    unsigned ub = (unsigned)__bfloat16_as_ushort(b);
    return ua | (ub << 16);
}
__device__ __forceinline__ void split_store(char* dh, char* dl, const float* xs) {
    unsigned hw[8], lw[8];
#pragma unroll
    for (int j = 0; j < 8; ++j) {
        __nv_bfloat16 h0 = __float2bfloat16(xs[j * 2 + 0]);
        __nv_bfloat16 h1 = __float2bfloat16(xs[j * 2 + 1]);
        __nv_bfloat16 l0 = __float2bfloat16(xs[j * 2 + 0] - __bfloat162float(h0));
        __nv_bfloat16 l1 = __float2bfloat16(xs[j * 2 + 1] - __bfloat162float(h1));
        hw[j] = pack_bf2(h0, h1);
        lw[j] = pack_bf2(l0, l1);
    }
    *(uint4*)dh        = make_uint4(hw[0], hw[1], hw[2], hw[3]);
    *(uint4*)(dh + 16) = make_uint4(hw[4], hw[5], hw[6], hw[7]);
    *(uint4*)dl        = make_uint4(lw[0], lw[1], lw[2], lw[3]);
    *(uint4*)(dl + 16) = make_uint4(lw[4], lw[5], lw[6], lw[7]);
}

// ---------------------------------------------------------------------------
// k0: split W_msg (24576) and W_lin (16384) into hi/lo bf16 images
// ---------------------------------------------------------------------------
__global__ __launch_bounds__(256) void k0_prep_w(const float* __restrict__ W_msg,
                                                 const float* __restrict__ W_lin) {
    int idx = blockIdx.x * 256 + threadIdx.x;      // 0..40959
    float x;
    if (idx < 24576) x = W_msg[idx];
    else             x = W_lin[idx - 24576];
    __nv_bfloat16 h = __float2bfloat16(x);
    __nv_bfloat16 l = __float2bfloat16(x - __bfloat162float(h));
    if (idx < 16384) {
        ((__nv_bfloat16*)g_W1img_hi)[idx] = h;
        ((__nv_bfloat16*)g_W1img_lo)[idx] = l;
    } else if (idx < 24576) {
        ((__nv_bfloat16*)g_Bimg_hi)[idx - 16384] = h;
        ((__nv_bfloat16*)g_Bimg_lo)[idx - 16384] = l;
    } else {
        ((__nv_bfloat16*)g_WLimg_hi)[idx - 24576] = h;
        ((__nv_bfloat16*)g_WLimg_lo)[idx - 24576] = l;
    }
}

// ---------------------------------------------------------------------------
// shared 128x128 HMMA GEMM body (K=128), 512 threads.
// CTA = 128 rows x 128 cols, 16 warps (4m x 4n), warp = 32r x 32c.
// ---------------------------------------------------------------------------
#define KQ_APITCH 272
#define KQ_BPITCH 272
#define KQ_AHI 0
#define KQ_ALO 34816
#define KQ_BHI 69632
#define KQ_BLO 104448
#define KQ_SMEM 139264

#define HMMA_128x128_BODY(SRC, BIMG_HI, BIMG_LO)                                   \
    const int tid = threadIdx.x;                                                   \
    const int lane = tid & 31, w = tid >> 5;                                       \
    {                                                                              \
        const uint4* bh = BIMG_HI;                                                 \
        const uint4* bl = BIMG_LO;                                                 \
        _Pragma("unroll")                                                          \
        for (int t = 0; t < 4; ++t) {                                              \
            int idx = tid + t * 512;                                               \
            int row = idx >> 4, seg = idx & 15;                                    \
            *(uint4*)(smc + KQ_BHI + row * KQ_BPITCH + seg * 16) = bh[idx];        \
            *(uint4*)(smc + KQ_BLO + row * KQ_BPITCH + seg * 16) = bl[idx];        \
        }                                                                          \
    }                                                                              \
    {                                                                              \
        int r = tid >> 2, q = tid & 3;                                             \
        int gr = row0 + r;                                                         \
        float xs[32];                                                              \
        if (gr < NN) {                                                             \
            const float4* p = (const float4*)(SRC + (size_t)gr * 128 + q * 32);    \
            _Pragma("unroll")                                                      \
            for (int i = 0; i < 8; ++i) {                                          \
                float4 f = p[i];                                                   \
                xs[i*4+0]=f.x; xs[i*4+1]=f.y; xs[i*4+2]=f.z; xs[i*4+3]=f.w;        \
            }                                                                      \
        } else {                                                                   \
            _Pragma("unroll")                                                      \
            for (int i = 0; i < 32; ++i) xs[i] = 0.f;                              \
        }                                                                          \
        split_store(smc + KQ_AHI + r * KQ_APITCH + q * 64,                         \
                    smc + KQ_ALO + r * KQ_APITCH + q * 64, xs);                    \
        split_store(smc + KQ_AHI + r * KQ_APITCH + q * 64 + 32,                    \
                    smc + KQ_ALO + r * KQ_APITCH + q * 64 + 32, xs + 16);          \
    }                                                                              \
    __syncthreads();                                                               \
    const int m0 = (w >> 2) * 32;                                                  \
    const int n0 = (w & 3) * 32;                                                   \
    float acc[2][4][4];                                                            \
    _Pragma("unroll")                                                              \
    for (int a = 0; a < 2; ++a)                                                    \
        _Pragma("unroll")                                                          \
        for (int b = 0; b < 4; ++b)                                                \
            _Pragma("unroll")                                                      \
            for (int c = 0; c < 4; ++c) acc[a][b][c] = 0.f;                        \
    const uint32_t arow = (uint32_t)(lane & 15);                                   \
    const uint32_t acol = (uint32_t)((lane >> 4) * 16);                            \
    _Pragma("unroll")                                                              \
    for (int k = 0; k < 8; ++k) {                                                  \
        uint32_t a0[4], a1[4];                                                     \
        uint32_t ad = sb + KQ_AHI + (uint32_t)(m0 + arow) * KQ_APITCH + k * 32 + acol; \
        ldsm_x4(ad, a0);                                                           \
        ldsm_x4(ad + 16 * KQ_APITCH, a1);                                          \
        _Pragma("unroll")                                                          \
        for (int p = 0; p < 2; ++p) {                                              \
            uint32_t bd = sb + KQ_BHI + (uint32_t)(k * 16 + arow) * KQ_BPITCH      \
                        + (uint32_t)(n0 + p * 16) * 2 + acol;                      \
            uint32_t h0,h1,h2,h3, l0,l1,l2,l3;                                     \
            ldsm_x4_t(bd, h0, h1, h2, h3);                                         \
            ldsm_x4_t(bd + (KQ_BLO - KQ_BHI), l0, l1, l2, l3);                     \
            mma16816(acc[0][p*2],   a0, h0, h1);                                   \
            mma16816(acc[0][p*2+1], a0, h2, h3);                                   \
            mma16816(acc[1][p*2],   a1, h0, h1);                                   \
            mma16816(acc[1][p*2+1], a1, h2, h3);                                   \
            mma16816(acc[0][p*2],   a0, l0, l1);                                   \
            mma16816(acc[0][p*2+1], a0, l2, l3);                                   \
            mma16816(acc[1][p*2],   a1, l0, l1);                                   \
            mma16816(acc[1][p*2+1], a1, l2, l3);                                   \
        }                                                                          \
    }                                                                              \
    _Pragma("unroll")                                                              \
    for (int k = 0; k < 8; ++k) {                                                  \
        uint32_t a0[4], a1[4];                                                     \
        uint32_t ad = sb + KQ_ALO + (uint32_t)(m0 + arow) * KQ_APITCH + k * 32 + acol; \
        ldsm_x4(ad, a0);                                                           \
        ldsm_x4(ad + 16 * KQ_APITCH, a1);                                          \
        _Pragma("unroll")                                                          \
        for (int p = 0; p < 2; ++p) {                                              \
            uint32_t bd = sb + KQ_BHI + (uint32_t)(k * 16 + arow) * KQ_BPITCH      \
                        + (uint32_t)(n0 + p * 16) * 2 + acol;                      \
            uint32_t h0,h1,h2,h3;                                                  \
            ldsm_x4_t(bd, h0, h1, h2, h3);                                         \
            mma16816(acc[0][p*2],   a0, h0, h1);                                   \
            mma16816(acc[0][p*2+1], a0, h2, h3);                                   \
            mma16816(acc[1][p*2],   a1, h0, h1);                                   \
            mma16816(acc[1][p*2+1], a1, h2, h3);                                   \
        }                                                                          \
    }

// ---------------------------------------------------------------------------
// k1: H1 = hidden @ W1 + b_msg   (128-row CTA, 512 thr)
// ---------------------------------------------------------------------------
__global__ __launch_bounds__(512, 1) void k1_node_hmma(
    const float* __restrict__ A, const float* __restrict__ bias,
    float* __restrict__ out)
{
    extern __shared__ char smc[];
    const uint32_t sb = smem_u32(smc);
    const int row0 = blockIdx.x * 128;
    HMMA_128x128_BODY(A, g_W1img_hi, g_W1img_lo)

#pragma unroll
    for (int mt = 0; mt < 2; ++mt) {
#pragma unroll
        for (int half = 0; half < 2; ++half) {
            int r = row0 + m0 + mt * 16 + (lane >> 2) + half * 8;
            if (r < NN) {
                float* o = out + (size_t)r * 128;
#pragma unroll
                for (int nt = 0; nt < 4; ++nt) {
                    int j = n0 + nt * 8 + (lane & 3) * 2;
                    float2 b2 = *(const float2*)(bias + j);
                    float2 v;
                    v.x = acc[mt][nt][half * 2 + 0] + b2.x;
                    v.y = acc[mt][nt][half * 2 + 1] + b2.y;
                    *(float2*)(o + j) = v;
                }
            }
        }
    }
}

// ---------------------------------------------------------------------------
// k2: split-bf16 edge GEMM (HMMA), 512 thr / 16 warps, warp = 16 edges x 32c.
// __launch_bounds__(512,2): 64 regs/thr, 2 CTAs/SM = 32 warps/SM (max).
// gather H1[src], relu, red.v2 scatter. Dropout mask: W = tile*16 + w.
// ---------------------------------------------------------------------------
#define K2_APITCH 144
#define K2_BPITCH 272
#define K2_AHI 0
#define K2_ALO 9216
#define K2_BHI 18432
#define K2_BLO 35840
#define K2_IDX 53248
#define K2_SMEM 53760

__global__ __launch_bounds__(512, 2) void k2_edge_mma(
    const float* __restrict__ eattr, const float* __restrict__ etime,
    const int* __restrict__ eidx, const float* __restrict__ H1,
    float* __restrict__ accum)
{
    extern __shared__ char smc[];
    const uint32_t sb = smem_u32(smc);
    const int tid = threadIdx.x;
    const int lane = tid & 31, w = tid >> 5;
    const int e0 = blockIdx.x * 64;
    int* s_src = (int*)(smc + K2_IDX);
    int* s_dst = s_src + 64;

    if (tid < 128) {
        int r = tid & 63;
        int e = e0 + r;
        int v = (e < NE) ? eidx[(tid < 64 ? 0 : NE) + e] : 0;
        if (tid < 64) s_src[r] = v; else s_dst[r] = v;
    }
    // B images -> smem (1024 uint4 each, 512 threads -> 2 each)
    {
        const uint4* bh = g_Bimg_hi;
        const uint4* bl = g_Bimg_lo;
#pragma unroll
        for (int t = 0; t < 2; ++t) {
            int idx = tid + t * 512;
            int row = idx >> 4, seg = idx & 15;
            *(uint4*)(smc + K2_BHI + row * K2_BPITCH + seg * 16) = bh[idx];
            *(uint4*)(smc + K2_BLO + row * K2_BPITCH + seg * 16) = bl[idx];
        }
    }
    // A tile: 64 edges x 64 f32; thread: ed=tid>>3, q=tid&7 (8 floats each)
    {
        int ed = tid >> 3, q = tid & 7;
        int e = e0 + ed;
        float xs[8];
        if (e < NE) {
            const float4* p = (q < 4) ? ((const float4*)(eattr + (size_t)e * 32) + q * 2)
                                      : ((const float4*)(etime + (size_t)e * 32) + (q - 4) * 2);
            float4 f0 = p[0], f1 = p[1];
            xs[0]=f0.x; xs[1]=f0.y; xs[2]=f0.z; xs[3]=f0.w;
            xs[4]=f1.x; xs[5]=f1.y; xs[6]=f1.z; xs[7]=f1.w;
        } else {
#pragma unroll
            for (int i = 0; i < 8; ++i) xs[i] = 0.f;
        }
        // split 8 floats -> 4+4 packed words into hi/lo at q*32..q*32+15
        unsigned hw[4], lw[4];
#pragma unroll
        for (int j = 0; j < 4; ++j) {
            __nv_bfloat16 h0 = __float2bfloat16(xs[j * 2 + 0]);
            __nv_bfloat16 h1 = __float2bfloat16(xs[j * 2 + 1]);
            __nv_bfloat16 l0 = __float2bfloat16(xs[j * 2 + 0] - __bfloat162float(h0));
            __nv_bfloat16 l1 = __float2bfloat16(xs[j * 2 + 1] - __bfloat162float(h1));
            hw[j] = pack_bf2(h0, h1);
            lw[j] = pack_bf2(l0, l1);
        }
        *(uint4*)(smc + K2_AHI + ed * K2_APITCH + q * 16) = make_uint4(hw[0], hw[1], hw[2], hw[3]);
        *(uint4*)(smc + K2_ALO + ed * K2_APITCH + q * 16) = make_uint4(lw[0], lw[1], lw[2], lw[3]);
    }
    // dropout keep-mask for node row W = tile*16 + w (16 warps)
    {
        int W = blockIdx.x * 16 + w;
        if (W < NN) {
#pragma unroll
            for (int k = 0; k < 4; ++k) {
                unsigned flat = (unsigned)(W * 128 + lane * 4 + k);
                unsigned bits = threefry_bits(flat);
                float u = __uint_as_float((bits >> 9) | 0x3F800000u) - 1.0f;
                unsigned bal = __ballot_sync(0xffffffffu, u < 0.9f);
                if (lane == k) g_mask[W * 4 + k] = bal;
            }
        }
    }
    __syncthreads();

    const int m0 = (w >> 2) * 16;     // 0,16,32,48
    const int n0 = (w & 3) * 32;

    float acc[4][4];
#pragma unroll
    for (int b = 0; b < 4; ++b)
#pragma unroll
        for (int c = 0; c < 4; ++c) acc[b][c] = 0.f;

    const uint32_t arow = (uint32_t)(lane & 15);
    const uint32_t acol = (uint32_t)((lane >> 4) * 16);

    // pass 1: ahi x (bhi + blo)
#pragma unroll
    for (int k = 0; k < 4; ++k) {
        uint32_t a0[4];
        ldsm_x4(sb + K2_AHI + (uint32_t)(m0 + arow) * K2_APITCH + k * 32 + acol, a0);
#pragma unroll
        for (int p = 0; p < 2; ++p) {
            uint32_t bd = sb + K2_BHI + (uint32_t)(k * 16 + arow) * K2_BPITCH
                        + (uint32_t)(n0 + p * 16) * 2 + acol;
            uint32_t h0,h1,h2,h3, l0,l1,l2,l3;
            ldsm_x4_t(bd, h0, h1, h2, h3);
            ldsm_x4_t(bd + (K2_BLO - K2_BHI), l0, l1, l2, l3);
            mma16816(acc[p*2],   a0, h0, h1);
            mma16816(acc[p*2+1], a0, h2, h3);
            mma16816(acc[p*2],   a0, l0, l1);
            mma16816(acc[p*2+1], a0, l2, l3);
        }
    }
    // pass 2: alo x bhi
#pragma unroll
    for (int k = 0; k < 4; ++k) {
        uint32_t a0[4];
        ldsm_x4(sb + K2_ALO + (uint32_t)(m0 + arow) * K2_APITCH + k * 32 + acol, a0);
#pragma unroll
        for (int p = 0; p < 2; ++p) {
            uint32_t bd = sb + K2_BHI + (uint32_t)(k * 16 + arow) * K2_BPITCH
                        + (uint32_t)(n0 + p * 16) * 2 + acol;
            uint32_t h0,h1,h2,h3;
            ldsm_x4_t(bd, h0, h1, h2, h3);
            mma16816(acc[p*2],   a0, h0, h1);
            mma16816(acc[p*2+1], a0, h2, h3);
        }
    }

    // epilogue: gather H1[src], relu, red.v2 into acc[dst]
#pragma unroll
    for (int half = 0; half < 2; ++half) {
        int r = m0 + (lane >> 2) + half * 8;
        if (e0 + r < NE) {
            const float* hp = H1 + (size_t)s_src[r] * 128;
            float* ap = accum + (size_t)s_dst[r] * 128;
#pragma unroll
            for (int nt = 0; nt < 4; ++nt) {
                int j = n0 + nt * 8 + (lane & 3) * 2;
                float2 h = *(const float2*)(hp + j);
                red_add_v2(ap + j,
                           fmaxf(acc[nt][half * 2 + 0] + h.x, 0.f),
                           fmaxf(acc[nt][half * 2 + 1] + h.y, 0.f));
            }
        }
    }
}

// ---------------------------------------------------------------------------
// k3: out = dropout(relu(LN(acc @ W_lin + b_lin)))  — 128-row CTA, 512 thr,
// smem-staged LN epilogue (warp per row), mask read from g_mask.
// ---------------------------------------------------------------------------
#define K3_OPITCH 132

__global__ __launch_bounds__(512, 1) void k3_hmma(
    const float* __restrict__ A, const float* __restrict__ bias,
    const float* __restrict__ gamma, const float* __restrict__ beta,
    float* __restrict__ out)
{
    extern __shared__ char smc[];
    const uint32_t sb = smem_u32(smc);
    const int row0 = blockIdx.x * 128;
    HMMA_128x128_BODY(A, g_WLimg_hi, g_WLimg_lo)

    __syncthreads();
    float* so = (float*)smc;
#pragma unroll
    for (int mt = 0; mt < 2; ++mt) {
#pragma unroll
        for (int half = 0; half < 2; ++half) {
            int rl = m0 + mt * 16 + (lane >> 2) + half * 8;
#pragma unroll
            for (int nt = 0; nt < 4; ++nt) {
                int j = n0 + nt * 8 + (lane & 3) * 2;
                float2 v;
                v.x = acc[mt][nt][half * 2 + 0];
                v.y = acc[mt][nt][half * 2 + 1];
                *(float2*)(so + rl * K3_OPITCH + j) = v;
            }
        }
    }
    __syncthreads();

    const int tx = lane;
    float bb[4] = { bias[tx], bias[tx + 32], bias[tx + 64], bias[tx + 96] };
    float gm[4] = { gamma[tx], gamma[tx + 32], gamma[tx + 64], gamma[tx + 96] };
    float bt[4] = { beta[tx],  beta[tx + 32],  beta[tx + 64],  beta[tx + 96] };

#pragma unroll
    for (int i = 0; i < 8; ++i) {
        int rl = w * 8 + i;
        int r = row0 + rl;
        float v[4];
#pragma unroll
        for (int c = 0; c < 4; ++c) v[c] = so[rl * K3_OPITCH + tx + 32 * c] + bb[c];
        float s = v[0] + v[1] + v[2] + v[3];
#pragma unroll
        for (int off = 16; off; off >>= 1) s += __shfl_xor_sync(0xffffffffu, s, off);
        float mean = s * (1.0f / 128.0f);
        float d[4];
        float ss = 0.f;
#pragma unroll
        for (int c = 0; c < 4; ++c) { d[c] = v[c] - mean; ss += d[c] * d[c]; }
#pragma unroll
        for (int off = 16; off; off >>= 1) ss += __shfl_xor_sync(0xffffffffu, ss, off);
        float rstd = rsqrtf(ss * (1.0f / 128.0f) + 1e-5f);

        if (r < NN) {
            float* o = out + (size_t)r * 128;
            unsigned mw = g_mask[r * 4 + (tx & 3)];
#pragma unroll
            for (int c = 0; c < 4; ++c) {
                int j = tx + 32 * c;
                float y = d[c] * rstd * gm[c] + bt[c];
                y = fmaxf(y, 0.f);
                unsigned bit = (unsigned)(8 * c + (tx >> 2));
                o[j] = ((mw >> bit) & 1u) ? (y * (1.0f / 0.9f)) : 0.f;
            }
        }
    }
}

// ---------------------------------------------------------------------------
extern "C" void kernel_launch(void* const* d_in, const int* in_sizes, int n_in,
                              void* d_out, int out_size) {
    (void)in_sizes; (void)n_in; (void)out_size;
    const float* hidden   = (const float*)d_in[0];
    const int*   eidx     = (const int*)d_in[1];
    const float* eattr    = (const float*)d_in[2];
    const float* etime    = (const float*)d_in[3];
    const float* boundary = (const float*)d_in[4];
    const float* W_msg    = (const float*)d_in[5];
    const float* b_msg    = (const float*)d_in[6];
    const float* W_lin    = (const float*)d_in[7];
    const float* b_lin    = (const float*)d_in[8];
    const float* gamma    = (const float*)d_in[9];
    const float* beta     = (const float*)d_in[10];
    float* out = (float*)d_out;

    void* h1Ptr = nullptr;
    void* accPtr = nullptr;
    cudaGetSymbolAddress(&h1Ptr, g_H1);
    cudaGetSymbolAddress(&accPtr, g_acc);

    cudaFuncSetAttribute(k1_node_hmma, cudaFuncAttributeMaxDynamicSharedMemorySize, KQ_SMEM);
    cudaFuncSetAttribute(k2_edge_mma,  cudaFuncAttributeMaxDynamicSharedMemorySize, K2_SMEM);
    cudaFuncSetAttribute(k3_hmma,      cudaFuncAttributeMaxDynamicSharedMemorySize, KQ_SMEM);

    // acc = boundary_condition (self-loop messages)
    cudaMemcpyAsync(accPtr, boundary, (size_t)NN * EMBD * sizeof(float),
                    cudaMemcpyDeviceToDevice, 0);

    // prep: split W_msg + W_lin into bf16 hi/lo images
    k0_prep_w<<<160, 256>>>(W_msg, W_lin);

    // H1 = hidden @ W_msg[0:128] + b_msg   (HMMA, 128-row CTAs)
    k1_node_hmma<<<(NN + 127) / 128, 512, KQ_SMEM>>>(hidden, b_msg, (float*)h1Ptr);

    // edge messages: 16-warp CTAs, 2/SM = 32 warps/SM + red.v2 scatter + mask
    k2_edge_mma<<<(NE + 63) / 64, 512, K2_SMEM>>>(eattr, etime, eidx,
                                                  (const float*)h1Ptr, (float*)accPtr);

    // node update: HMMA GEMM + LN + relu + mask-dropout (128-row CTAs)
    k3_hmma<<<(NN + 127) / 128, 512, KQ_SMEM>>>((const float*)accPtr, b_lin,
                                                gamma, beta, out);
}

// round 13
// speedup vs baseline: 1.0679x; 1.0403x over previous
#include <cuda_runtime.h>
#include <cuda_bf16.h>
#include <cstdint>

#define NN  50000
#define EMBD 128
#define NE  500000

// scratch (allocation-free rule: __device__ globals)
__device__ __align__(16) float g_H1[NN * EMBD];
__device__ __align__(16) float g_acc[NN * EMBD];
__device__ unsigned g_mask[NN * 4];   // dropout keep-bits, 4 words/row
// pre-split bf16 images (row-major [k][n])
__device__ __align__(16) uint4 g_W1img_hi[2048];  // 32KB, W_msg[0:128,:]
__device__ __align__(16) uint4 g_W1img_lo[2048];
__device__ __align__(16) uint4 g_Bimg_hi[1024];   // 16KB, W_msg[128:192,:]
__device__ __align__(16) uint4 g_Bimg_lo[1024];
__device__ __align__(16) uint4 g_WLimg_hi[2048];  // 32KB, W_lin
__device__ __align__(16) uint4 g_WLimg_lo[2048];

// ---------------------------------------------------------------------------
// threefry2x32, JAX partitionable mode. key=(0,42), counter=(0, flat),
// output = out0 ^ out1.
// ---------------------------------------------------------------------------
__device__ __forceinline__ unsigned tf_rotl(unsigned x, int r) {
    return __funnelshift_l(x, x, r);
}
__device__ __forceinline__ unsigned threefry_bits(unsigned flat) {
    unsigned x0 = 0u, x1 = flat;
    const unsigned ks0 = 0u, ks1 = 42u, ks2 = 0x1BD11BDAu ^ 0u ^ 42u;
    x0 += ks0; x1 += ks1;
#define TF_R(r) { x0 += x1; x1 = tf_rotl(x1, r); x1 ^= x0; }
    TF_R(13) TF_R(15) TF_R(26) TF_R(6)
    x0 += ks1; x1 += ks2 + 1u;
    TF_R(17) TF_R(29) TF_R(16) TF_R(24)
    x0 += ks2; x1 += ks0 + 2u;
    TF_R(13) TF_R(15) TF_R(26) TF_R(6)
    x0 += ks0; x1 += ks1 + 3u;
    TF_R(17) TF_R(29) TF_R(16) TF_R(24)
    x0 += ks1; x1 += ks2 + 4u;
    TF_R(13) TF_R(15) TF_R(26) TF_R(6)
    x0 += ks2; x1 += ks0 + 5u;
#undef TF_R
    return x0 ^ x1;
}

// ---------------------------------------------------------------------------
// baseline-PTX helpers
// ---------------------------------------------------------------------------
__device__ __forceinline__ uint32_t smem_u32(const void* p) {
    uint32_t a;
    asm("{ .reg .u64 t; cvta.to.shared.u64 t, %1; cvt.u32.u64 %0, t; }"
        : "=r"(a) : "l"(p));
    return a;
}
__device__ __forceinline__ void ldsm_x4(uint32_t addr, uint32_t* r) {
    asm volatile("ldmatrix.sync.aligned.m8n8.x4.shared.b16 {%0,%1,%2,%3}, [%4];"
                 : "=r"(r[0]), "=r"(r[1]), "=r"(r[2]), "=r"(r[3]) : "r"(addr));
}
__device__ __forceinline__ void ldsm_x4_t(uint32_t addr, uint32_t& r0, uint32_t& r1,
                                          uint32_t& r2, uint32_t& r3) {
    asm volatile("ldmatrix.sync.aligned.m8n8.x4.trans.shared.b16 {%0,%1,%2,%3}, [%4];"
                 : "=r"(r0), "=r"(r1), "=r"(r2), "=r"(r3) : "r"(addr));
}
__device__ __forceinline__ void mma16816(float* c, const uint32_t* a,
                                         uint32_t b0, uint32_t b1) {
    asm volatile(
        "mma.sync.aligned.m16n8k16.row.col.f32.bf16.bf16.f32 "
        "{%0,%1,%2,%3}, {%4,%5,%6,%7}, {%8,%9}, {%0,%1,%2,%3};"
        : "+f"(c[0]), "+f"(c[1]), "+f"(c[2]), "+f"(c[3])
        : "r"(a[0]), "r"(a[1]), "r"(a[2]), "r"(a[3]), "r"(b0), "r"(b1));
}
__device__ __forceinline__ void red_add_v2(float* p, float a, float b) {
    asm volatile("red.global.add.v2.f32 [%0], {%1, %2};"
                 :: "l"(p), "f"(a), "f"(b) : "memory");
}
__device__ __forceinline__ unsigned pack_bf2(__nv_bfloat16 a, __nv_bfloat16 b) {
    unsigned ua = (unsigned)__bfloat16_as_ushort(a);
    unsigned ub = (unsigned)__bfloat16_as_ushort(b);
    return ua | (ub << 16);
}
__device__ __forceinline__ void split_store(char* dh, char* dl, const float* xs) {
    unsigned hw[8], lw[8];
#pragma unroll
    for (int j = 0; j < 8; ++j) {
        __nv_bfloat16 h0 = __float2bfloat16(xs[j * 2 + 0]);
        __nv_bfloat16 h1 = __float2bfloat16(xs[j * 2 + 1]);
        __nv_bfloat16 l0 = __float2bfloat16(xs[j * 2 + 0] - __bfloat162float(h0));
        __nv_bfloat16 l1 = __float2bfloat16(xs[j * 2 + 1] - __bfloat162float(h1));
        hw[j] = pack_bf2(h0, h1);
        lw[j] = pack_bf2(l0, l1);
    }
    *(uint4*)dh        = make_uint4(hw[0], hw[1], hw[2], hw[3]);
    *(uint4*)(dh + 16) = make_uint4(hw[4], hw[5], hw[6], hw[7]);
    *(uint4*)dl        = make_uint4(lw[0], lw[1], lw[2], lw[3]);
    *(uint4*)(dl + 16) = make_uint4(lw[4], lw[5], lw[6], lw[7]);
}

// ---------------------------------------------------------------------------
// k0: split W_msg (24576) and W_lin (16384) into hi/lo bf16 images
// ---------------------------------------------------------------------------
__global__ __launch_bounds__(256) void k0_prep_w(const float* __restrict__ W_msg,
                                                 const float* __restrict__ W_lin) {
    int idx = blockIdx.x * 256 + threadIdx.x;      // 0..40959
    float x;
    if (idx < 24576) x = W_msg[idx];
    else             x = W_lin[idx - 24576];
    __nv_bfloat16 h = __float2bfloat16(x);
    __nv_bfloat16 l = __float2bfloat16(x - __bfloat162float(h));
    if (idx < 16384) {
        ((__nv_bfloat16*)g_W1img_hi)[idx] = h;
        ((__nv_bfloat16*)g_W1img_lo)[idx] = l;
    } else if (idx < 24576) {
        ((__nv_bfloat16*)g_Bimg_hi)[idx - 16384] = h;
        ((__nv_bfloat16*)g_Bimg_lo)[idx - 16384] = l;
    } else {
        ((__nv_bfloat16*)g_WLimg_hi)[idx - 24576] = h;
        ((__nv_bfloat16*)g_WLimg_lo)[idx - 24576] = l;
    }
}

// ---------------------------------------------------------------------------
// shared 128x128 HMMA GEMM body (K=128), 512 threads.
// CTA = 128 rows x 128 cols, 16 warps (4m x 4n), warp = 32r x 32c.
// ---------------------------------------------------------------------------
#define KQ_APITCH 272
#define KQ_BPITCH 272
#define KQ_AHI 0
#define KQ_ALO 34816
#define KQ_BHI 69632
#define KQ_BLO 104448
#define KQ_SMEM 139264

#define HMMA_128x128_BODY(SRC, BIMG_HI, BIMG_LO)                                   \
    const int tid = threadIdx.x;                                                   \
    const int lane = tid & 31, w = tid >> 5;                                       \
    {                                                                              \
        const uint4* bh = BIMG_HI;                                                 \
        const uint4* bl = BIMG_LO;                                                 \
        _Pragma("unroll")                                                          \
        for (int t = 0; t < 4; ++t) {                                              \
            int idx = tid + t * 512;                                               \
            int row = idx >> 4, seg = idx & 15;                                    \
            *(uint4*)(smc + KQ_BHI + row * KQ_BPITCH + seg * 16) = bh[idx];        \
            *(uint4*)(smc + KQ_BLO + row * KQ_BPITCH + seg * 16) = bl[idx];        \
        }                                                                          \
    }                                                                              \
    {                                                                              \
        int r = tid >> 2, q = tid & 3;                                             \
        int gr = row0 + r;                                                         \
        float xs[32];                                                              \
        if (gr < NN) {                                                             \
            const float4* p = (const float4*)(SRC + (size_t)gr * 128 + q * 32);    \
            _Pragma("unroll")                                                      \
            for (int i = 0; i < 8; ++i) {                                          \
                float4 f = p[i];                                                   \
                xs[i*4+0]=f.x; xs[i*4+1]=f.y; xs[i*4+2]=f.z; xs[i*4+3]=f.w;        \
            }                                                                      \
        } else {                                                                   \
            _Pragma("unroll")                                                      \
            for (int i = 0; i < 32; ++i) xs[i] = 0.f;                              \
        }                                                                          \
        split_store(smc + KQ_AHI + r * KQ_APITCH + q * 64,                         \
                    smc + KQ_ALO + r * KQ_APITCH + q * 64, xs);                    \
        split_store(smc + KQ_AHI + r * KQ_APITCH + q * 64 + 32,                    \
                    smc + KQ_ALO + r * KQ_APITCH + q * 64 + 32, xs + 16);          \
    }                                                                              \
    __syncthreads();                                                               \
    const int m0 = (w >> 2) * 32;                                                  \
    const int n0 = (w & 3) * 32;                                                   \
    float acc[2][4][4];                                                            \
    _Pragma("unroll")                                                              \
    for (int a = 0; a < 2; ++a)                                                    \
        _Pragma("unroll")                                                          \
        for (int b = 0; b < 4; ++b)                                                \
            _Pragma("unroll")                                                      \
            for (int c = 0; c < 4; ++c) acc[a][b][c] = 0.f;                        \
    const uint32_t arow = (uint32_t)(lane & 15);                                   \
    const uint32_t acol = (uint32_t)((lane >> 4) * 16);                            \
    _Pragma("unroll")                                                              \
    for (int k = 0; k < 8; ++k) {                                                  \
        uint32_t a0[4], a1[4];                                                     \
        uint32_t ad = sb + KQ_AHI + (uint32_t)(m0 + arow) * KQ_APITCH + k * 32 + acol; \
        ldsm_x4(ad, a0);                                                           \
        ldsm_x4(ad + 16 * KQ_APITCH, a1);                                          \
        _Pragma("unroll")                                                          \
        for (int p = 0; p < 2; ++p) {                                              \
            uint32_t bd = sb + KQ_BHI + (uint32_t)(k * 16 + arow) * KQ_BPITCH      \
                        + (uint32_t)(n0 + p * 16) * 2 + acol;                      \
            uint32_t h0,h1,h2,h3, l0,l1,l2,l3;                                     \
            ldsm_x4_t(bd, h0, h1, h2, h3);                                         \
            ldsm_x4_t(bd + (KQ_BLO - KQ_BHI), l0, l1, l2, l3);                     \
            mma16816(acc[0][p*2],   a0, h0, h1);                                   \
            mma16816(acc[0][p*2+1], a0, h2, h3);                                   \
            mma16816(acc[1][p*2],   a1, h0, h1);                                   \
            mma16816(acc[1][p*2+1], a1, h2, h3);                                   \
            mma16816(acc[0][p*2],   a0, l0, l1);                                   \
            mma16816(acc[0][p*2+1], a0, l2, l3);                                   \
            mma16816(acc[1][p*2],   a1, l0, l1);                                   \
            mma16816(acc[1][p*2+1], a1, l2, l3);                                   \
        }                                                                          \
    }                                                                              \
    _Pragma("unroll")                                                              \
    for (int k = 0; k < 8; ++k) {                                                  \
        uint32_t a0[4], a1[4];                                                     \
        uint32_t ad = sb + KQ_ALO + (uint32_t)(m0 + arow) * KQ_APITCH + k * 32 + acol; \
        ldsm_x4(ad, a0);                                                           \
        ldsm_x4(ad + 16 * KQ_APITCH, a1);                                          \
        _Pragma("unroll")                                                          \
        for (int p = 0; p < 2; ++p) {                                              \
            uint32_t bd = sb + KQ_BHI + (uint32_t)(k * 16 + arow) * KQ_BPITCH      \
                        + (uint32_t)(n0 + p * 16) * 2 + acol;                      \
            uint32_t h0,h1,h2,h3;                                                  \
            ldsm_x4_t(bd, h0, h1, h2, h3);                                         \
            mma16816(acc[0][p*2],   a0, h0, h1);                                   \
            mma16816(acc[0][p*2+1], a0, h2, h3);                                   \
            mma16816(acc[1][p*2],   a1, h0, h1);                                   \
            mma16816(acc[1][p*2+1], a1, h2, h3);                                   \
        }                                                                          \
    }

// ---------------------------------------------------------------------------
// k1: H1 = hidden @ W1 + b_msg   (128-row CTA, 512 thr)
//     + folds acc = boundary (removes the serial memcpy)
// ---------------------------------------------------------------------------
__global__ __launch_bounds__(512, 1) void k1_node_hmma(
    const float* __restrict__ A, const float* __restrict__ bias,
    const float* __restrict__ boundary, float* __restrict__ out,
    float* __restrict__ accum)
{
    extern __shared__ char smc[];
    const uint32_t sb = smem_u32(smc);
    const int row0 = blockIdx.x * 128;
    HMMA_128x128_BODY(A, g_W1img_hi, g_W1img_lo)

#pragma unroll
    for (int mt = 0; mt < 2; ++mt) {
#pragma unroll
        for (int half = 0; half < 2; ++half) {
            int r = row0 + m0 + mt * 16 + (lane >> 2) + half * 8;
            if (r < NN) {
                float* o = out + (size_t)r * 128;
                float* ac = accum + (size_t)r * 128;
                const float* bd = boundary + (size_t)r * 128;
#pragma unroll
                for (int nt = 0; nt < 4; ++nt) {
                    int j = n0 + nt * 8 + (lane & 3) * 2;
                    float2 b2 = *(const float2*)(bias + j);
                    float2 v;
                    v.x = acc[mt][nt][half * 2 + 0] + b2.x;
                    v.y = acc[mt][nt][half * 2 + 1] + b2.y;
                    *(float2*)(o + j) = v;
                    *(float2*)(ac + j) = *(const float2*)(bd + j);
                }
            }
        }
    }
}

// ---------------------------------------------------------------------------
// k2: split-bf16 edge GEMM (HMMA) + gather/relu + red.v2 scatter.
// CTA = 64 edges x 128 cols, 256 thr, 8 warps (2m x 4n); 3 CTAs/SM.
// Also generates the dropout keep-mask.  (exact R10 config)
// ---------------------------------------------------------------------------
#define K2_APITCH 144
#define K2_BPITCH 272
#define K2_AHI 0
#define K2_ALO 9216
#define K2_BHI 18432
#define K2_BLO 35840
#define K2_IDX 53248
#define K2_SMEM 53760

__global__ __launch_bounds__(256, 3) void k2_edge_mma(
    const float* __restrict__ eattr, const float* __restrict__ etime,
    const int* __restrict__ eidx, const float* __restrict__ H1,
    float* __restrict__ accum)
{
    extern __shared__ char smc[];
    const uint32_t sb = smem_u32(smc);
    const int tid = threadIdx.x;
    const int lane = tid & 31, w = tid >> 5;
    const int e0 = blockIdx.x * 64;
    int* s_src = (int*)(smc + K2_IDX);
    int* s_dst = s_src + 64;

    if (tid < 128) {
        int r = tid & 63;
        int e = e0 + r;
        int v = (e < NE) ? eidx[(tid < 64 ? 0 : NE) + e] : 0;
        if (tid < 64) s_src[r] = v; else s_dst[r] = v;
    }
    {
        const uint4* bh = g_Bimg_hi;
        const uint4* bl = g_Bimg_lo;
#pragma unroll
        for (int t = 0; t < 4; ++t) {
            int idx = tid + t * 256;
            int row = idx >> 4, seg = idx & 15;
            *(uint4*)(smc + K2_BHI + row * K2_BPITCH + seg * 16) = bh[idx];
            *(uint4*)(smc + K2_BLO + row * K2_BPITCH + seg * 16) = bl[idx];
        }
    }
    {
        int ed = tid >> 2, q = tid & 3;
        int e = e0 + ed;
        float xs[16];
        if (e < NE) {
            const float4* p = (q < 2) ? ((const float4*)(eattr + (size_t)e * 32) + q * 4)
                                      : ((const float4*)(etime + (size_t)e * 32) + (q - 2) * 4);
            float4 f0 = p[0], f1 = p[1], f2 = p[2], f3 = p[3];
            xs[0]=f0.x; xs[1]=f0.y; xs[2]=f0.z; xs[3]=f0.w;
            xs[4]=f1.x; xs[5]=f1.y; xs[6]=f1.z; xs[7]=f1.w;
            xs[8]=f2.x; xs[9]=f2.y; xs[10]=f2.z; xs[11]=f2.w;
            xs[12]=f3.x; xs[13]=f3.y; xs[14]=f3.z; xs[15]=f3.w;
        } else {
#pragma unroll
            for (int i = 0; i < 16; ++i) xs[i] = 0.f;
        }
        split_store(smc + K2_AHI + ed * K2_APITCH + q * 32,
                    smc + K2_ALO + ed * K2_APITCH + q * 32, xs);
    }

    // dropout keep-mask for node row W (one warp per row)
    {
        int W = blockIdx.x * 8 + w;
        if (W < NN) {
#pragma unroll
            for (int k = 0; k < 4; ++k) {
                unsigned flat = (unsigned)(W * 128 + lane * 4 + k);
                unsigned bits = threefry_bits(flat);
                float u = __uint_as_float((bits >> 9) | 0x3F800000u) - 1.0f;
                unsigned bal = __ballot_sync(0xffffffffu, u < 0.9f);
                if (lane == k) g_mask[W * 4 + k] = bal;
            }
        }
    }
    __syncthreads();

    const int m0 = (w >> 2) * 32;
    const int n0 = (w & 3) * 32;

    float acc[2][4][4];
#pragma unroll
    for (int a = 0; a < 2; ++a)
#pragma unroll
        for (int b = 0; b < 4; ++b)
#pragma unroll
            for (int c = 0; c < 4; ++c) acc[a][b][c] = 0.f;

    const uint32_t arow = (uint32_t)(lane & 15);
    const uint32_t acol = (uint32_t)((lane >> 4) * 16);

#pragma unroll
    for (int k = 0; k < 4; ++k) {
        uint32_t a0[4], a1[4];
        uint32_t ad = sb + K2_AHI + (uint32_t)(m0 + arow) * K2_APITCH + k * 32 + acol;
        ldsm_x4(ad, a0);
        ldsm_x4(ad + 16 * K2_APITCH, a1);
#pragma unroll
        for (int p = 0; p < 2; ++p) {
            uint32_t bd = sb + K2_BHI + (uint32_t)(k * 16 + arow) * K2_BPITCH
                        + (uint32_t)(n0 + p * 16) * 2 + acol;
            uint32_t h0,h1,h2,h3, l0,l1,l2,l3;
            ldsm_x4_t(bd, h0, h1, h2, h3);
            ldsm_x4_t(bd + (K2_BLO - K2_BHI), l0, l1, l2, l3);
            mma16816(acc[0][p*2],   a0, h0, h1);
            mma16816(acc[0][p*2+1], a0, h2, h3);
            mma16816(acc[1][p*2],   a1, h0, h1);
            mma16816(acc[1][p*2+1], a1, h2, h3);
            mma16816(acc[0][p*2],   a0, l0, l1);
            mma16816(acc[0][p*2+1], a0, l2, l3);
            mma16816(acc[1][p*2],   a1, l0, l1);
            mma16816(acc[1][p*2+1], a1, l2, l3);
        }
    }
#pragma unroll
    for (int k = 0; k < 4; ++k) {
        uint32_t a0[4], a1[4];
        uint32_t ad = sb + K2_ALO + (uint32_t)(m0 + arow) * K2_APITCH + k * 32 + acol;
        ldsm_x4(ad, a0);
        ldsm_x4(ad + 16 * K2_APITCH, a1);
#pragma unroll
        for (int p = 0; p < 2; ++p) {
            uint32_t bd = sb + K2_BHI + (uint32_t)(k * 16 + arow) * K2_BPITCH
                        + (uint32_t)(n0 + p * 16) * 2 + acol;
            uint32_t h0,h1,h2,h3;
            ldsm_x4_t(bd, h0, h1, h2, h3);
            mma16816(acc[0][p*2],   a0, h0, h1);
            mma16816(acc[0][p*2+1], a0, h2, h3);
            mma16816(acc[1][p*2],   a1, h0, h1);
            mma16816(acc[1][p*2+1], a1, h2, h3);
        }
    }

    // epilogue: gather H1[src], relu, red.v2 into acc[dst]
#pragma unroll
    for (int mt = 0; mt < 2; ++mt) {
#pragma unroll
        for (int half = 0; half < 2; ++half) {
            int r = m0 + mt * 16 + (lane >> 2) + half * 8;
            if (e0 + r < NE) {
                const float* hp = H1 + (size_t)s_src[r] * 128;
                float* ap = accum + (size_t)s_dst[r] * 128;
#pragma unroll
                for (int nt = 0; nt < 4; ++nt) {
                    int j = n0 + nt * 8 + (lane & 3) * 2;
                    float2 h = *(const float2*)(hp + j);
                    red_add_v2(ap + j,
                               fmaxf(acc[mt][nt][half * 2 + 0] + h.x, 0.f),
                               fmaxf(acc[mt][nt][half * 2 + 1] + h.y, 0.f));
                }
            }
        }
    }
}

// ---------------------------------------------------------------------------
// k3: out = dropout(relu(LN(acc @ W_lin + b_lin)))  — 128-row CTA, 512 thr,
// smem-staged LN epilogue (warp per row), mask read from g_mask.
// ---------------------------------------------------------------------------
#define K3_OPITCH 132

__global__ __launch_bounds__(512, 1) void k3_hmma(
    const float* __restrict__ A, const float* __restrict__ bias,
    const float* __restrict__ gamma, const float* __restrict__ beta,
    float* __restrict__ out)
{
    extern __shared__ char smc[];
    const uint32_t sb = smem_u32(smc);
    const int row0 = blockIdx.x * 128;
    HMMA_128x128_BODY(A, g_WLimg_hi, g_WLimg_lo)

    __syncthreads();
    float* so = (float*)smc;
#pragma unroll
    for (int mt = 0; mt < 2; ++mt) {
#pragma unroll
        for (int half = 0; half < 2; ++half) {
            int rl = m0 + mt * 16 + (lane >> 2) + half * 8;
#pragma unroll
            for (int nt = 0; nt < 4; ++nt) {
                int j = n0 + nt * 8 + (lane & 3) * 2;
                float2 v;
                v.x = acc[mt][nt][half * 2 + 0];
                v.y = acc[mt][nt][half * 2 + 1];
                *(float2*)(so + rl * K3_OPITCH + j) = v;
            }
        }
    }
    __syncthreads();

    const int tx = lane;
    float bb[4] = { bias[tx], bias[tx + 32], bias[tx + 64], bias[tx + 96] };
    float gm[4] = { gamma[tx], gamma[tx + 32], gamma[tx + 64], gamma[tx + 96] };
    float bt[4] = { beta[tx],  beta[tx + 32],  beta[tx + 64],  beta[tx + 96] };

#pragma unroll
    for (int i = 0; i < 8; ++i) {
        int rl = w * 8 + i;
        int r = row0 + rl;
        float v[4];
#pragma unroll
        for (int c = 0; c < 4; ++c) v[c] = so[rl * K3_OPITCH + tx + 32 * c] + bb[c];
        float s = v[0] + v[1] + v[2] + v[3];
#pragma unroll
        for (int off = 16; off; off >>= 1) s += __shfl_xor_sync(0xffffffffu, s, off);
        float mean = s * (1.0f / 128.0f);
        float d[4];
        float ss = 0.f;
#pragma unroll
        for (int c = 0; c < 4; ++c) { d[c] = v[c] - mean; ss += d[c] * d[c]; }
#pragma unroll
        for (int off = 16; off; off >>= 1) ss += __shfl_xor_sync(0xffffffffu, ss, off);
        float rstd = rsqrtf(ss * (1.0f / 128.0f) + 1e-5f);

        if (r < NN) {
            float* o = out + (size_t)r * 128;
            unsigned mw = g_mask[r * 4 + (tx & 3)];
#pragma unroll
            for (int c = 0; c < 4; ++c) {
                int j = tx + 32 * c;
                float y = d[c] * rstd * gm[c] + bt[c];
                y = fmaxf(y, 0.f);
                unsigned bit = (unsigned)(8 * c + (tx >> 2));
                o[j] = ((mw >> bit) & 1u) ? (y * (1.0f / 0.9f)) : 0.f;
            }
        }
    }
}

// ---------------------------------------------------------------------------
extern "C" void kernel_launch(void* const* d_in, const int* in_sizes, int n_in,
                              void* d_out, int out_size) {
    (void)in_sizes; (void)n_in; (void)out_size;
    const float* hidden   = (const float*)d_in[0];
    const int*   eidx     = (const int*)d_in[1];
    const float* eattr    = (const float*)d_in[2];
    const float* etime    = (const float*)d_in[3];
    const float* boundary = (const float*)d_in[4];
    const float* W_msg    = (const float*)d_in[5];
    const float* b_msg    = (const float*)d_in[6];
    const float* W_lin    = (const float*)d_in[7];
    const float* b_lin    = (const float*)d_in[8];
    const float* gamma    = (const float*)d_in[9];
    const float* beta     = (const float*)d_in[10];
    float* out = (float*)d_out;

    void* h1Ptr = nullptr;
    void* accPtr = nullptr;
    cudaGetSymbolAddress(&h1Ptr, g_H1);
    cudaGetSymbolAddress(&accPtr, g_acc);

    cudaFuncSetAttribute(k1_node_hmma, cudaFuncAttributeMaxDynamicSharedMemorySize, KQ_SMEM);
    cudaFuncSetAttribute(k2_edge_mma,  cudaFuncAttributeMaxDynamicSharedMemorySize, K2_SMEM);
    cudaFuncSetAttribute(k3_hmma,      cudaFuncAttributeMaxDynamicSharedMemorySize, KQ_SMEM);

    // prep: split W_msg + W_lin into bf16 hi/lo images
    k0_prep_w<<<160, 256>>>(W_msg, W_lin);

    // H1 = hidden @ W_msg[0:128] + b_msg   (HMMA) + acc = boundary (folded)
    k1_node_hmma<<<(NN + 127) / 128, 512, KQ_SMEM>>>(hidden, b_msg, boundary,
                                                     (float*)h1Ptr, (float*)accPtr);

    // edge messages (HMMA split-bf16, 3 CTAs/SM) + red.v2 scatter + mask gen
    k2_edge_mma<<<(NE + 63) / 64, 256, K2_SMEM>>>(eattr, etime, eidx,
                                                  (const float*)h1Ptr, (float*)accPtr);

    // node update: HMMA GEMM + LN + relu + mask-dropout (128-row CTAs)
    k3_hmma<<<(NN + 127) / 128, 512, KQ_SMEM>>>((const float*)accPtr, b_lin,
                                                gamma, beta, out);
}